// round 5
// baseline (speedup 1.0000x reference)
#include <cuda_runtime.h>
#include <cuda.h>
#include <cuda_fp16.h>
#include <cstdint>

// ---------------- problem constants ----------------
#define NTOK   16384
#define DIN    512
#define DOUT   512
#define KEXP   8
#define KTOT   4160            // 8*512 + 64 pad; cols 4096..4103 carry coeffs->bias
#define KC     64              // fp16 elems per K chunk = 128 bytes (SW128 atom)
#define NCHUNK 65              // KTOT / KC
#define TILE_M 128
#define TILE_N 128
#define NSTAGE 3
#define A_BYTES     (TILE_M * 128)       // 16 KB
#define B_BYTES     (TILE_N * 128)       // 16 KB
#define STAGE_BYTES (A_BYTES + B_BYTES)  // 32 KB
#define DYN_BYTES   (NSTAGE * STAGE_BYTES + 1024)

// ---------------- device scratch ----------------
__device__ __half g_xc[(size_t)NTOK * KTOT];   // fp16 coeff-scaled X, K-extended
__device__ __half g_wc[(size_t)DOUT * KTOT];   // fp16 stacked weights + bias cols

// ---------------- PTX helpers (all sm_90-baseline or older; NO tcgen05) ----------------
__device__ __forceinline__ uint32_t smem_u32(const void* p) {
    uint32_t a;
    asm("{ .reg .u64 t; cvta.to.shared.u64 t, %1; cvt.u32.u64 %0, t; }" : "=r"(a) : "l"(p));
    return a;
}

#define MBAR_INIT(addr, cnt) \
    asm volatile("mbarrier.init.shared.b64 [%0], %1;" :: "r"(addr), "r"(cnt) : "memory")
#define MBAR_EXPECT_TX(addr, bytes) \
    asm volatile("mbarrier.arrive.expect_tx.shared.b64 _, [%0], %1;" :: "r"(addr), "r"(bytes) : "memory")
#define MBAR_ARRIVE(addr) \
    asm volatile("mbarrier.arrive.shared.b64 _, [%0];" :: "r"(addr) : "memory")

#define MBAR_WAIT(addr, parity) do {                                              \
    uint32_t _m = (uint32_t)(addr);                                               \
    uint32_t _p = (uint32_t)(parity);                                             \
    uint32_t _done;                                                               \
    asm volatile("{\n\t.reg .pred p;\n\t"                                         \
        "mbarrier.try_wait.parity.acquire.cta.shared::cta.b64 p, [%1], %2;\n\t"   \
        "selp.b32 %0, 1, 0, p;\n\t}"                                              \
        : "=r"(_done) : "r"(_m), "r"(_p) : "memory");                             \
    if (!_done) {                                                                 \
        asm volatile("{\n\t.reg .pred P1;\n\t"                                    \
            "WAIT_LOOP_%=:\n\t"                                                   \
            "mbarrier.try_wait.parity.acquire.cta.shared::cta.b64 P1, [%0], %1, 0x989680;\n\t" \
            "@P1 bra.uni WAIT_DONE_%=;\n\t"                                       \
            "bra.uni WAIT_LOOP_%=;\n\t"                                           \
            "WAIT_DONE_%=:\n\t}"                                                  \
            :: "r"(_m), "r"(_p) : "memory");                                      \
    }                                                                             \
} while (0)

#define TMA2D(dst, map, cx, cy, bar) \
    asm volatile("cp.async.bulk.tensor.2d.shared::cta.global.tile.mbarrier::complete_tx::bytes " \
        "[%0], [%1, {%2, %3}], [%4];" \
        :: "r"(dst), "l"(map), "r"(cx), "r"(cy), "r"(bar) : "memory")

#define LDSM_X4(r, addr) \
    asm volatile("ldmatrix.sync.aligned.m8n8.x4.shared.b16 {%0,%1,%2,%3}, [%4];" \
        : "=r"((r)[0]), "=r"((r)[1]), "=r"((r)[2]), "=r"((r)[3]) : "r"(addr))

__device__ __forceinline__ void mma16816(float* d, const uint32_t* a, const uint32_t* b) {
    asm volatile("mma.sync.aligned.m16n8k16.row.col.f32.f16.f16.f32 "
        "{%0,%1,%2,%3}, {%4,%5,%6,%7}, {%8,%9}, {%0,%1,%2,%3};"
        : "+f"(d[0]), "+f"(d[1]), "+f"(d[2]), "+f"(d[3])
        : "r"(a[0]), "r"(a[1]), "r"(a[2]), "r"(a[3]), "r"(b[0]), "r"(b[1]));
}

// ---------------- kernel 1: gating softmax (fp32) + pack coeff-scaled X to fp16 ----------------
__global__ void __launch_bounds__(256) prep_x_kernel(
    const float* __restrict__ x,
    const float* __restrict__ mixer_w,
    const float* __restrict__ mixer_b)
{
    __shared__ float sw[KEXP * DIN];
    __shared__ float sb[KEXP];
    const int tid = threadIdx.x;
    for (int i = tid; i < KEXP * DIN; i += 256) sw[i] = mixer_w[i];
    if (tid < KEXP) sb[tid] = mixer_b[tid];
    __syncthreads();

    const int warp = tid >> 5, lane = tid & 31;
    const int t = blockIdx.x * 8 + warp;
    const float2* xr2 = reinterpret_cast<const float2*>(x + (size_t)t * DIN);

    float2 xv[8];
    #pragma unroll
    for (int ii = 0; ii < 8; ii++) xv[ii] = xr2[ii * 32 + lane];

    float acc[KEXP];
    #pragma unroll
    for (int e = 0; e < KEXP; e++) acc[e] = 0.f;
    #pragma unroll
    for (int ii = 0; ii < 8; ii++) {
        const int i = ii * 64 + lane * 2;
        #pragma unroll
        for (int e = 0; e < KEXP; e++)
            acc[e] += xv[ii].x * sw[e * DIN + i] + xv[ii].y * sw[e * DIN + i + 1];
    }
    #pragma unroll
    for (int off = 16; off > 0; off >>= 1) {
        #pragma unroll
        for (int e = 0; e < KEXP; e++)
            acc[e] += __shfl_xor_sync(0xffffffffu, acc[e], off);
    }
    float lg[KEXP];
    #pragma unroll
    for (int e = 0; e < KEXP; e++) lg[e] = acc[e] + sb[e];
    float mx = lg[0];
    #pragma unroll
    for (int e = 1; e < KEXP; e++) mx = fmaxf(mx, lg[e]);
    float p[KEXP], s = 0.f;
    #pragma unroll
    for (int e = 0; e < KEXP; e++) { p[e] = __expf(lg[e] - mx); s += p[e]; }
    const float inv = 1.f / s;
    float c[KEXP];
    #pragma unroll
    for (int e = 0; e < KEXP; e++) c[e] = p[e] * inv;

    __half* orow = g_xc + (size_t)t * KTOT;
    #pragma unroll
    for (int e = 0; e < KEXP; e++) {
        __half2* dst = reinterpret_cast<__half2*>(orow + e * DIN);
        #pragma unroll
        for (int ii = 0; ii < 8; ii++)
            dst[ii * 32 + lane] = __floats2half2_rn(c[e] * xv[ii].x, c[e] * xv[ii].y);
    }
    // tail cols [4096, 4160): first 8 = coeffs (bias path), rest zero
    {
        __half2 v = (lane < 4) ? __floats2half2_rn(c[2 * lane], c[2 * lane + 1])
                               : __floats2half2_rn(0.f, 0.f);
        reinterpret_cast<__half2*>(orow + 4096)[lane] = v;
    }
}

// ---------------- kernel 2: pack stacked weights + bias columns to fp16 ----------------
__global__ void __launch_bounds__(256) prep_w_kernel(
    const float* __restrict__ W,     // [8][512][512]  (e, o, i)
    const float* __restrict__ bz)    // [8][512]
{
    const int o = blockIdx.x;
    const int tid = threadIdx.x;
    __half* orow = g_wc + (size_t)o * KTOT;
    #pragma unroll
    for (int e = 0; e < KEXP; e++) {
        const float* src = W + ((size_t)e * DOUT + o) * DIN;
        for (int i = tid; i < DIN; i += 256)
            orow[e * DIN + i] = __float2half_rn(src[i]);
    }
    if (tid < 64)
        orow[4096 + tid] = (tid < KEXP) ? __float2half_rn(bz[tid * DOUT + o])
                                        : __float2half_rn(0.f);
}

// ---------------- kernel 3: single big fp16 GEMM (M=16384, N=512, K=4160) ----------------
__global__ void __launch_bounds__(256, 2) moe_gemm_kernel(
    const __grid_constant__ CUtensorMap a_map,
    const __grid_constant__ CUtensorMap b_map,
    float* __restrict__ out)
{
    extern __shared__ char dyn_smem[];
    __shared__ __align__(8) unsigned long long s_bars[2 * NSTAGE];

    const int tid = threadIdx.x;
    const int w   = tid >> 5;
    const int l   = tid & 31;
    const int ntile = blockIdx.x;   // 0..3
    const int mtile = blockIdx.y;   // 0..127

    const uint32_t base = (smem_u32(dyn_smem) + 1023u) & ~1023u;
    const uint32_t bars = smem_u32(s_bars);
    // full[s] = bars + s*8 ; empty[s] = bars + NSTAGE*8 + s*8

    if (tid == 0) {
        #pragma unroll
        for (int s = 0; s < NSTAGE; s++) {
            MBAR_INIT(bars + s * 8, 1);                 // full: 1 tx-completion
            MBAR_INIT(bars + (NSTAGE + s) * 8, 8);      // empty: 8 warp arrivals
        }
    }
    __syncthreads();

    if (tid == 0) {
        #pragma unroll
        for (int s = 0; s < NSTAGE; s++) {
            const uint32_t fb = bars + s * 8;
            MBAR_EXPECT_TX(fb, STAGE_BYTES);
            TMA2D(base + s * STAGE_BYTES,           &a_map, s * KC, mtile * TILE_M, fb);
            TMA2D(base + s * STAGE_BYTES + A_BYTES, &b_map, s * KC, ntile * TILE_N, fb);
        }
    }

    // per-lane fragment addressing (SW128: within 128B row, 16B seg s -> s ^ (row&7))
    const int wm = (w & 1) * 64;
    const int wn = (w >> 1) * 32;
    int rA[4], rB[2];
    #pragma unroll
    for (int mi = 0; mi < 4; mi++) rA[mi] = wm + mi * 16 + (l & 15);
    #pragma unroll
    for (int nj2 = 0; nj2 < 2; nj2++)
        rB[nj2] = wn + nj2 * 16 + ((l >> 4) & 1) * 8 + (l & 7);
    const int segA = (l >> 4);         // 0/1 : k-seg offset within 16-k step
    const int segB = (l >> 3) & 1;

    float acc[4][4][4];
    #pragma unroll
    for (int mi = 0; mi < 4; mi++)
        #pragma unroll
        for (int nj = 0; nj < 4; nj++)
            #pragma unroll
            for (int q = 0; q < 4; q++) acc[mi][nj][q] = 0.f;

    for (int ch = 0; ch < NCHUNK; ch++) {
        const int s = ch % NSTAGE;
        const uint32_t ph = (uint32_t)((ch / NSTAGE) & 1);
        const uint32_t fb = bars + s * 8;
        const uint32_t eb = bars + (NSTAGE + s) * 8;
        const uint32_t Ab = base + s * STAGE_BYTES;
        const uint32_t Bb = Ab + A_BYTES;

        MBAR_WAIT(fb, ph);

        #pragma unroll
        for (int kk = 0; kk < 4; kk++) {
            const int s0 = kk * 2;
            uint32_t ar[4][4], br[2][4];
            #pragma unroll
            for (int mi = 0; mi < 4; mi++) {
                uint32_t addr = Ab + rA[mi] * 128 + ((uint32_t)((s0 + segA) ^ (rA[mi] & 7)) << 4);
                LDSM_X4(ar[mi], addr);
            }
            #pragma unroll
            for (int nj2 = 0; nj2 < 2; nj2++) {
                uint32_t addr = Bb + rB[nj2] * 128 + ((uint32_t)((s0 + segB) ^ (rB[nj2] & 7)) << 4);
                LDSM_X4(br[nj2], addr);
            }
            #pragma unroll
            for (int mi = 0; mi < 4; mi++)
                #pragma unroll
                for (int nj = 0; nj < 4; nj++)
                    mma16816(acc[mi][nj], ar[mi], &br[nj >> 1][(nj & 1) * 2]);
        }

        if (l == 0) MBAR_ARRIVE(eb);
        if (tid == 0 && ch + NSTAGE < NCHUNK) {
            MBAR_WAIT(eb, ph);                    // consumption of this stage complete
            MBAR_EXPECT_TX(fb, STAGE_BYTES);
            TMA2D(Ab, &a_map, (ch + NSTAGE) * KC, mtile * TILE_M, fb);
            TMA2D(Bb, &b_map, (ch + NSTAGE) * KC, ntile * TILE_N, fb);
        }
    }

    // epilogue: direct fp32 store (bias already folded into K-extension)
    const int row0 = mtile * TILE_M + wm + (l >> 2);
    const int col0 = ntile * TILE_N + wn + 2 * (l & 3);
    #pragma unroll
    for (int mi = 0; mi < 4; mi++) {
        #pragma unroll
        for (int nj = 0; nj < 4; nj++) {
            float2 v0 = make_float2(acc[mi][nj][0], acc[mi][nj][1]);
            float2 v1 = make_float2(acc[mi][nj][2], acc[mi][nj][3]);
            *reinterpret_cast<float2*>(out + (size_t)(row0 + mi * 16) * DOUT + col0 + nj * 8) = v0;
            *reinterpret_cast<float2*>(out + (size_t)(row0 + mi * 16 + 8) * DOUT + col0 + nj * 8) = v1;
        }
    }
}

// ---------------- host launcher ----------------
typedef CUresult (*PFN_tmapEncode)(
    CUtensorMap*, CUtensorMapDataType, cuuint32_t, void*,
    const cuuint64_t*, const cuuint64_t*, const cuuint32_t*, const cuuint32_t*,
    CUtensorMapInterleave, CUtensorMapSwizzle, CUtensorMapL2promotion, CUtensorMapFloatOOBfill);

extern "C" void kernel_launch(void* const* d_in, const int* in_sizes, int n_in,
                              void* d_out, int out_size)
{
    const float* x  = (const float*)d_in[0];   // [16384, 512]
    const float* W  = (const float*)d_in[1];   // [8, 512, 512]
    const float* bz = (const float*)d_in[2];   // [8, 512]
    const float* mw = (const float*)d_in[3];   // [8, 512]
    const float* mb = (const float*)d_in[4];   // [8]
    float* out = (float*)d_out;
    (void)in_sizes; (void)n_in; (void)out_size;

    void* xc_ptr = nullptr; void* wc_ptr = nullptr;
    cudaGetSymbolAddress(&xc_ptr, g_xc);
    cudaGetSymbolAddress(&wc_ptr, g_wc);

    prep_x_kernel<<<NTOK / 8, 256>>>(x, mw, mb);
    prep_w_kernel<<<DOUT, 256>>>(W, bz);

    void* fnp = nullptr;
    cudaDriverEntryPointQueryResult st;
    cudaGetDriverEntryPointByVersion("cuTensorMapEncodeTiled", &fnp, 12000,
                                     cudaEnableDefault, &st);
    PFN_tmapEncode enc = (PFN_tmapEncode)fnp;

    CUtensorMap a_map, b_map;
    {
        cuuint64_t dims[2]    = { KTOT, NTOK };
        cuuint64_t strides[1] = { KTOT * sizeof(__half) };   // 8320 B
        cuuint32_t box[2]     = { KC, TILE_M };              // 64 x 128 (128B inner)
        cuuint32_t es[2]      = { 1, 1 };
        enc(&a_map, CU_TENSOR_MAP_DATA_TYPE_UINT16, 2, xc_ptr,
            dims, strides, box, es,
            CU_TENSOR_MAP_INTERLEAVE_NONE, CU_TENSOR_MAP_SWIZZLE_128B,
            CU_TENSOR_MAP_L2_PROMOTION_L2_128B, CU_TENSOR_MAP_FLOAT_OOB_FILL_NONE);
    }
    {
        cuuint64_t dims[2]    = { KTOT, DOUT };
        cuuint64_t strides[1] = { KTOT * sizeof(__half) };
        cuuint32_t box[2]     = { KC, TILE_N };
        cuuint32_t es[2]      = { 1, 1 };
        enc(&b_map, CU_TENSOR_MAP_DATA_TYPE_UINT16, 2, wc_ptr,
            dims, strides, box, es,
            CU_TENSOR_MAP_INTERLEAVE_NONE, CU_TENSOR_MAP_SWIZZLE_128B,
            CU_TENSOR_MAP_L2_PROMOTION_L2_128B, CU_TENSOR_MAP_FLOAT_OOB_FILL_NONE);
    }

    cudaFuncSetAttribute(moe_gemm_kernel, cudaFuncAttributeMaxDynamicSharedMemorySize, DYN_BYTES);
    dim3 grid(DOUT / TILE_N, NTOK / TILE_M);   // (4, 128)
    moe_gemm_kernel<<<grid, 256, DYN_BYTES>>>(a_map, b_map, out);
}